// round 9
// baseline (speedup 1.0000x reference)
#include <cuda_runtime.h>
#include <stdint.h>

#define X_COORD_START 10
#define Y_COORD_START 21
#define EOS_TOKEN     39
#define MAX_REACH     5.0f
#define WINDOW_SIZE   4
#define PENALTY_SCALE 1.0f

#define ROW_LEN   2048   // tokens per row
#define NTHREADS  128    // 4 warps, one row per CTA
#define WCHUNKS   4      // int4 chunks per warp
#define SEGSTRIDE 260    // 4 halo slots + up to 256 compacted pairs

// Self-resetting scratch (zero at module load; last CTA resets after each
// launch so every graph replay starts from zero — deterministic).
__device__ double        g_total   = 0.0;
__device__ int           g_nvs     = 0;
__device__ unsigned int  g_counter = 0;

__device__ __forceinline__ bool is_valid(int x, int y) {
    return ((unsigned)(x - X_COORD_START) < (unsigned)(Y_COORD_START - X_COORD_START)) &
           ((unsigned)(y - Y_COORD_START) < (unsigned)(EOS_TOKEN - Y_COORD_START));
}

__global__ __launch_bounds__(NTHREADS, 12)
void reach_loss_1row(const int* __restrict__ in, float* __restrict__ out,
                     int n_ctas) {
    const int t    = threadIdx.x;
    const int lane = t & 31;
    const int wid  = t >> 5;          // 0..3
    const unsigned lt = (1u << lane) - 1u;

    __shared__ int   seg[4 * SEGSTRIDE];  // warp-private compacted segments
    __shared__ int   scnt[4];
    __shared__ float wpart[4];

    const int* rowp = in + (size_t)blockIdx.x * ROW_LEN;

    // ---- Load this warp's quarter row: 4 independent LDG.128 ----
    int4 v[WCHUNKS];
    #pragma unroll
    for (int c = 0; c < WCHUNKS; c++)
        v[c] = reinterpret_cast<const int4*>(rowp)[(wid * WCHUNKS + c) * 32 + lane];

    // ---- Single-pass ballot compaction into warp-private segment ----
    // int4 q holds pair A = 2q-1 (tokens 4q,4q+1; q>=1) and pair B = 2q.
    int* myseg = &seg[wid * SEGSTRIDE];
    int cnt = 0;
    #pragma unroll
    for (int c = 0; c < WCHUNKS; c++) {
        const int4 p = v[c];
        const int q = (wid * WCHUNKS + c) * 32 + lane;
        const bool va = (q != 0) && is_valid(p.x, p.y);
        const bool vb = is_valid(p.z, p.w);
        const unsigned bA = __ballot_sync(0xffffffffu, va);
        const unsigned bB = __ballot_sync(0xffffffffu, vb);
        const int pos = cnt + __popc(bA & lt) + __popc(bB & lt);
        if (va) myseg[4 + pos]            = (p.y << 16) | p.x;
        if (vb) myseg[4 + pos + (va?1:0)] = (p.w << 16) | p.z;
        cnt += __popc(bA) + __popc(bB);
    }
    if (lane == 0) scnt[wid] = cnt;
    __syncthreads();

    const int s0 = scnt[0], s1 = scnt[1], s2 = scnt[2], s3 = scnt[3];
    const int prefix = (wid > 0 ? s0 : 0) + (wid > 1 ? s1 : 0)
                     + (wid > 2 ? s2 : 0);
    const int total = s0 + s1 + s2 + s3;

    // ---- Halo fill: lanes 0..3 fetch the 4 global predecessors of this
    //      warp's segment into slots 3-lane ----
    if (lane < 4) {
        const int gb = prefix - 1 - lane;   // global compacted index
        if (gb >= 0) {
            int w2, loc;
            if      (gb >= s0 + s1 + s2) { w2 = 3; loc = gb - (s0 + s1 + s2); }
            else if (gb >= s0 + s1)      { w2 = 2; loc = gb - (s0 + s1); }
            else if (gb >= s0)           { w2 = 1; loc = gb - s0; }
            else                         { w2 = 0; loc = gb; }
            myseg[3 - lane] = seg[w2 * SEGSTRIDE + 4 + loc];
        }
    }
    __syncwarp();

    // ---- Uniform window loop over this warp's local compacted pairs ----
    const int* s = myseg + 4;
    const int st = (4 - prefix) > 0 ? (4 - prefix) : 0;   // enforce global i>=4
    float vsum = 0.0f;
    for (int i = st + lane; i < cnt; i += 32) {
        const int pki = s[i];
        const int xi = pki & 0xffff;
        const int yi = pki >> 16;
        int msq = 0x7fffffff;
        #pragma unroll
        for (int j = 1; j <= WINDOW_SIZE; j++) {
            const int pkj = s[i - j];               // halo covers i-j in [-4,0)
            const int dx = xi - (pkj & 0xffff);
            const int dy = yi - (pkj >> 16);
            msq = min(msq, dx * dx + dy * dy);
        }
        // viol = max(sqrt(msq)-5, 0): exact 0 for msq <= 25 (incl. msq==0)
        vsum += fmaxf(sqrtf((float)msq) - MAX_REACH, 0.0f);
    }
    #pragma unroll
    for (int o = 16; o > 0; o >>= 1)
        vsum += __shfl_xor_sync(0xffffffffu, vsum, o);
    if (lane == 0) wpart[wid] = vsum;
    __syncthreads();

    // ---- One atomic pair per CTA; last CTA finalizes + resets ----
    if (t == 0) {
        if (total >= WINDOW_SIZE + 1) {
            const float pen = wpart[0] + wpart[1] + wpart[2] + wpart[3];
            atomicAdd(&g_total, (double)(pen / (float)(total - WINDOW_SIZE)));
            atomicAdd(&g_nvs, 1);
        }
        __threadfence();
        const unsigned ticket = atomicAdd(&g_counter, 1u);
        if (ticket == (unsigned)(n_ctas - 1)) {
            const double tot = *((volatile double*)&g_total);
            const int    tn  = *((volatile int*)&g_nvs);
            out[0] = (tn > 0) ? (float)(PENALTY_SCALE * tot / (double)tn) : 0.0f;
            g_total = 0.0;
            g_nvs   = 0;
            __threadfence();
            g_counter = 0u;
        }
    }
}

extern "C" void kernel_launch(void* const* d_in, const int* in_sizes, int n_in,
                              void* d_out, int out_size) {
    const int* in = (const int*)d_in[0];
    const int B = in_sizes[0] / ROW_LEN;   // 2048 rows = 2048 CTAs
    reach_loss_1row<<<B, NTHREADS>>>(in, (float*)d_out, B);
}

// round 10
// speedup vs baseline: 1.0909x; 1.0909x over previous
#include <cuda_runtime.h>
#include <stdint.h>

#define X_COORD_START 10
#define Y_COORD_START 21
#define EOS_TOKEN     39
#define MAX_REACH     5.0f
#define WINDOW_SIZE   4
#define PENALTY_SCALE 1.0f

#define ROW_LEN   2048   // tokens per row
#define NTHREADS  128    // 4 warps, one row per CTA
#define WCHUNKS   4      // int4 chunks per warp
#define SEGSTRIDE 260    // 4 halo slots + up to 256 compacted pairs
#define NBUCKETS  64
#define BSTRIDE   32     // doubles: 32*8 = 256B between buckets (avoid slice collide)
#define ISTRIDE   64     // ints: 64*4 = 256B

// Bucketed self-resetting scratch (zero at module load; last CTA resets all
// buckets after each launch — deterministic across graph replays).
__device__ double        g_bt[NBUCKETS * BSTRIDE];
__device__ int           g_bn[NBUCKETS * ISTRIDE];
__device__ unsigned int  g_counter = 0;

__device__ __forceinline__ bool is_valid(int x, int y) {
    return ((unsigned)(x - X_COORD_START) < (unsigned)(Y_COORD_START - X_COORD_START)) &
           ((unsigned)(y - Y_COORD_START) < (unsigned)(EOS_TOKEN - Y_COORD_START));
}

__global__ __launch_bounds__(NTHREADS, 12)
void reach_loss_bkt(const int* __restrict__ in, float* __restrict__ out,
                    int n_ctas) {
    const int t    = threadIdx.x;
    const int lane = t & 31;
    const int wid  = t >> 5;          // 0..3
    const unsigned lt = (1u << lane) - 1u;

    __shared__ int   seg[4 * SEGSTRIDE];  // warp-private compacted segments
    __shared__ int   scnt[4];
    __shared__ float wpart[4];
    __shared__ int   s_last;              // last-CTA flag
    __shared__ double s_red[2];

    const int* rowp = in + (size_t)blockIdx.x * ROW_LEN;

    // ---- Load this warp's quarter row: 4 independent LDG.128 ----
    int4 v[WCHUNKS];
    #pragma unroll
    for (int c = 0; c < WCHUNKS; c++)
        v[c] = reinterpret_cast<const int4*>(rowp)[(wid * WCHUNKS + c) * 32 + lane];

    // ---- Single-pass ballot compaction into warp-private segment ----
    // int4 q holds pair A = 2q-1 (tokens 4q,4q+1; q>=1) and pair B = 2q.
    int* myseg = &seg[wid * SEGSTRIDE];
    int cnt = 0;
    #pragma unroll
    for (int c = 0; c < WCHUNKS; c++) {
        const int4 p = v[c];
        const int q = (wid * WCHUNKS + c) * 32 + lane;
        const bool va = (q != 0) && is_valid(p.x, p.y);
        const bool vb = is_valid(p.z, p.w);
        const unsigned bA = __ballot_sync(0xffffffffu, va);
        const unsigned bB = __ballot_sync(0xffffffffu, vb);
        const int pos = cnt + __popc(bA & lt) + __popc(bB & lt);
        if (va) myseg[4 + pos]            = (p.y << 16) | p.x;
        if (vb) myseg[4 + pos + (va?1:0)] = (p.w << 16) | p.z;
        cnt += __popc(bA) + __popc(bB);
    }
    if (lane == 0) scnt[wid] = cnt;
    __syncthreads();

    const int s0 = scnt[0], s1 = scnt[1], s2 = scnt[2], s3 = scnt[3];
    const int prefix = (wid > 0 ? s0 : 0) + (wid > 1 ? s1 : 0)
                     + (wid > 2 ? s2 : 0);
    const int total = s0 + s1 + s2 + s3;

    // ---- Halo: lanes 0..3 fetch the 4 global predecessors of this segment ----
    if (lane < 4) {
        const int gb = prefix - 1 - lane;
        if (gb >= 0) {
            int w2, loc;
            if      (gb >= s0 + s1 + s2) { w2 = 3; loc = gb - (s0 + s1 + s2); }
            else if (gb >= s0 + s1)      { w2 = 2; loc = gb - (s0 + s1); }
            else if (gb >= s0)           { w2 = 1; loc = gb - s0; }
            else                         { w2 = 0; loc = gb; }
            myseg[3 - lane] = seg[w2 * SEGSTRIDE + 4 + loc];
        }
    }
    __syncwarp();

    // ---- Uniform window loop over this warp's local compacted pairs ----
    const int* s = myseg + 4;
    const int st = (4 - prefix) > 0 ? (4 - prefix) : 0;   // enforce global i>=4
    float vsum = 0.0f;
    for (int i = st + lane; i < cnt; i += 32) {
        const int pki = s[i];
        const int xi = pki & 0xffff;
        const int yi = pki >> 16;
        int msq = 0x7fffffff;
        #pragma unroll
        for (int j = 1; j <= WINDOW_SIZE; j++) {
            const int pkj = s[i - j];               // halo covers i-j in [-4,0)
            const int dx = xi - (pkj & 0xffff);
            const int dy = yi - (pkj >> 16);
            msq = min(msq, dx * dx + dy * dy);
        }
        vsum += fmaxf(sqrtf((float)msq) - MAX_REACH, 0.0f);  // exact 0 if msq<=25
    }
    #pragma unroll
    for (int o = 16; o > 0; o >>= 1)
        vsum += __shfl_xor_sync(0xffffffffu, vsum, o);
    if (lane == 0) wpart[wid] = vsum;
    __syncthreads();

    // ---- Bucketed fire-and-forget accumulation + single ticket ----
    if (t == 0) {
        const int b = blockIdx.x & (NBUCKETS - 1);
        if (total >= WINDOW_SIZE + 1) {
            const float pen = wpart[0] + wpart[1] + wpart[2] + wpart[3];
            atomicAdd(&g_bt[b * BSTRIDE],
                      (double)(pen / (float)(total - WINDOW_SIZE)));  // RED
            atomicAdd(&g_bn[b * ISTRIDE], 1);                          // RED
        }
        __threadfence();
        const unsigned ticket = atomicAdd(&g_counter, 1u);
        s_last = (ticket == (unsigned)(n_ctas - 1)) ? 1 : 0;
    }
    __syncthreads();

    // ---- Parallel finalize + reset by the last CTA ----
    if (s_last) {
        double bt = 0.0;
        int    bn = 0;
        if (t < NBUCKETS) {
            bt = *((volatile double*)&g_bt[t * BSTRIDE]);
            bn = *((volatile int*)&g_bn[t * ISTRIDE]);
            g_bt[t * BSTRIDE] = 0.0;   // reset for next replay
            g_bn[t * ISTRIDE] = 0;
        }
        // reduce 64 lanes (2 warps) via shfl + smem
        #pragma unroll
        for (int o = 16; o > 0; o >>= 1) {
            bt += __shfl_xor_sync(0xffffffffu, bt, o);
            bn += __shfl_xor_sync(0xffffffffu, bn, o);
        }
        if (t == 0)  { s_red[0] = bt; wpart[0] = (float)bn; }
        if (t == 32) { s_red[1] = bt; wpart[1] = (float)bn; }
        __syncthreads();
        if (t == 0) {
            const double tot = s_red[0] + s_red[1];
            const int    tn  = (int)wpart[0] + (int)wpart[1];
            out[0] = (tn > 0) ? (float)(PENALTY_SCALE * tot / (double)tn) : 0.0f;
            __threadfence();
            g_counter = 0u;
        }
    }
}

extern "C" void kernel_launch(void* const* d_in, const int* in_sizes, int n_in,
                              void* d_out, int out_size) {
    const int* in = (const int*)d_in[0];
    const int B = in_sizes[0] / ROW_LEN;   // 2048 rows = 2048 CTAs
    reach_loss_bkt<<<B, NTHREADS>>>(in, (float*)d_out, B);
}